// round 9
// baseline (speedup 1.0000x reference)
#include <cuda_runtime.h>
#include <math_constants.h>

#define KVOL 27
#define C4   24                 // 96 channels = 24 float4
#define RPB  16                 // rows per block: 24*16 = 384 threads
#define CAP  102400             // max n_out handled by the split path

// Scratch (static __device__ allocation — permitted by the harness rules).
__device__ int g_cnt[CAP];                    // per-row count of lo-half indices
__device__ int g_sorted[CAP * KVOL + 64];     // per-row: lo-packed then hi-packed

// L2 policy: keep in_feat lines resident (evict-last priority).
__device__ __forceinline__ unsigned long long mk_keep_policy() {
    unsigned long long pol;
    asm("createpolicy.fractional.L2::evict_last.b64 %0, 1.0;" : "=l"(pol));
    return pol;
}

// Gather load: bypass L1 (.cg) + evict_last L2 policy.
__device__ __forceinline__ float4 ldg_gather(const float4* p, unsigned long long pol) {
    float4 v;
    asm("ld.global.cg.L2::cache_hint.v4.f32 {%0,%1,%2,%3}, [%4], %5;"
        : "=f"(v.x), "=f"(v.y), "=f"(v.z), "=f"(v.w) : "l"(p), "l"(pol));
    return v;
}

__device__ __forceinline__ void vmax(float4& m, const float4 v) {
    m.x = fmaxf(m.x, v.x);
    m.y = fmaxf(m.y, v.y);
    m.z = fmaxf(m.z, v.z);
    m.w = fmaxf(m.w, v.w);
}

// ---------------- Preprocessing: partition each row's indices ----------------
// Packs indices < half at the front, >= half at the back (order irrelevant for max).
__global__ void partition_kernel(const void* __restrict__ nmap,
                                 int n_out, int n_in_rows, int half) {
    __shared__ int s_bad;
    int t = threadIdx.x;
    if (t == 0) s_bad = 0;
    __syncthreads();
    if (t < 64) {                       // dtype probe: int32-as-int64 goes out of range
        const long long* p = (const long long*)nmap;
        long long v = p[t];
        if (v < 0 || v >= (long long)n_in_rows) atomicOr(&s_bad, 1);
    }
    __syncthreads();
    bool is64 = (s_bad == 0);

    int r = blockIdx.x * blockDim.x + t;
    if (r >= n_out) return;
    int* dst = g_sorted + r * KVOL;
    int lo = 0, hi = KVOL;
    if (is64) {
        const long long* p = (const long long*)nmap + (long long)r * KVOL;
        #pragma unroll
        for (int k = 0; k < KVOL; ++k) {
            int v = (int)__ldcs(&p[k]);
            if (v < half) dst[lo++] = v; else dst[--hi] = v;
        }
    } else {
        const int* p = (const int*)nmap + (long long)r * KVOL;
        #pragma unroll
        for (int k = 0; k < KVOL; ++k) {
            int v = __ldcs(&p[k]);
            if (v < half) dst[lo++] = v; else dst[--hi] = v;
        }
    }
    g_cnt[r] = lo;
}

// ------------- Pooling pass over a packed contiguous index range -------------
template <int B>
__device__ __forceinline__ void gather_pred(const float4* __restrict__ feat,
                                            const int* __restrict__ nm,
                                            int k0, int kend,
                                            float4& m, unsigned long long pol) {
    const float4 NEG = make_float4(-CUDART_INF_F, -CUDART_INF_F,
                                   -CUDART_INF_F, -CUDART_INF_F);
    int idx[B];
    bool sel[B];
    #pragma unroll
    for (int j = 0; j < B; ++j) {
        sel[j] = (k0 + j) < kend;
        idx[j] = sel[j] ? __ldg(&nm[k0 + j]) : 0;
    }
    float4 v[B];
    #pragma unroll
    for (int j = 0; j < B; ++j)                        // up to B x 16B in flight
        v[j] = sel[j] ? ldg_gather(feat + (long long)idx[j] * C4, pol) : NEG;
    #pragma unroll
    for (int j = 0; j < B; ++j)
        vmax(m, v[j]);
}

template <bool COMBINE>
__global__ __launch_bounds__(C4 * RPB, 2)
void pool_pass(const float4* __restrict__ in_feat,
               float4* __restrict__ out, int n_out) {
    int row = blockIdx.x * RPB + threadIdx.y;
    if (row >= n_out) return;
    int c4 = threadIdx.x;

    const float4* feat_c = in_feat + c4;
    float4* outp = out + (long long)row * C4 + c4;
    const int* nm = g_sorted + row * KVOL;
    int cnt = g_cnt[row];
    int start = COMBINE ? cnt : 0;
    int end   = COMBINE ? KVOL : cnt;

    const unsigned long long pol = mk_keep_policy();
    float4 m = make_float4(-CUDART_INF_F, -CUDART_INF_F, -CUDART_INF_F, -CUDART_INF_F);
    if (COMBINE) m = __ldcs(outp);                     // partial from pass A

    gather_pred<14>(feat_c, nm, start,      end, m, pol);
    gather_pred<13>(feat_c, nm, start + 14, end, m, pol);
    __stcs(outp, m);
}

// ----------------- Fallback: direct single pass (R8 kernel) ------------------
__global__ __launch_bounds__(C4 * RPB, 2)
void pool_direct(const float4* __restrict__ in_feat,
                 const void* __restrict__ nmap,
                 float4* __restrict__ out, int n_out, int n_in_rows) {
    __shared__ int s_bad;
    int t = threadIdx.y * C4 + threadIdx.x;
    if (t == 0) s_bad = 0;
    __syncthreads();
    if (t < 64) {
        const long long* p = (const long long*)nmap;
        long long v = p[t];
        if (v < 0 || v >= (long long)n_in_rows) atomicOr(&s_bad, 1);
    }
    __syncthreads();
    bool is64 = (s_bad == 0);

    int row = blockIdx.x * RPB + threadIdx.y;
    if (row >= n_out) return;
    int c4 = threadIdx.x;
    const float4* feat_c = in_feat + c4;
    const unsigned long long pol = mk_keep_policy();
    float4 m = make_float4(-CUDART_INF_F, -CUDART_INF_F, -CUDART_INF_F, -CUDART_INF_F);
    if (is64) {
        const long long* nm = (const long long*)nmap + (long long)row * KVOL;
        int idx[KVOL];
        #pragma unroll
        for (int k = 0; k < KVOL; ++k) idx[k] = (int)__ldcs(&nm[k]);
        #pragma unroll
        for (int k = 0; k < KVOL; ++k)
            vmax(m, ldg_gather(feat_c + (long long)idx[k] * C4, pol));
    } else {
        const int* nm = (const int*)nmap + (long long)row * KVOL;
        int idx[KVOL];
        #pragma unroll
        for (int k = 0; k < KVOL; ++k) idx[k] = __ldcs(&nm[k]);
        #pragma unroll
        for (int k = 0; k < KVOL; ++k)
            vmax(m, ldg_gather(feat_c + (long long)idx[k] * C4, pol));
    }
    __stcs(out + (long long)row * C4 + c4, m);
}

extern "C" void kernel_launch(void* const* d_in, const int* in_sizes, int n_in,
                              void* d_out, int out_size) {
    const float4* in_feat = (const float4*)d_in[0];
    const void*   nmap    = (const void*)d_in[1];
    float4*       out     = (float4*)d_out;

    int nmap_elems = in_sizes[1];                      // N_OUT * KVOL
    int n_out      = nmap_elems / KVOL;                // 100000
    int n_in_rows  = in_sizes[0] / 96;                 // 400000
    int half       = n_in_rows / 2;

    dim3 block(C4, RPB);
    int grid = (n_out + RPB - 1) / RPB;

    if (n_out <= CAP) {
        partition_kernel<<<(n_out + 255) / 256, 256>>>(nmap, n_out, n_in_rows, half);
        // Pass A: gathers only feat rows [0, half)   -> 76.8 MB footprint
        pool_pass<false><<<grid, block>>>(in_feat, out, n_out);
        // Pass B: gathers only feat rows [half, end) -> 76.8 MB footprint
        pool_pass<true ><<<grid, block>>>(in_feat, out, n_out);
    } else {
        pool_direct<<<grid, block>>>(in_feat, nmap, out, n_out, n_in_rows);
    }
}

// round 10
// speedup vs baseline: 1.5663x; 1.5663x over previous
#include <cuda_runtime.h>
#include <math_constants.h>

#define KVOL 27
#define C4   24                 // 96 channels = 24 float4
#define RPB  16                 // rows per block: 24*16 = 384 threads

// L2 policy: keep in_feat lines resident (evict-last priority).
__device__ __forceinline__ unsigned long long mk_keep_policy() {
    unsigned long long pol;
    asm("createpolicy.fractional.L2::evict_last.b64 %0, 1.0;" : "=l"(pol));
    return pol;
}

// Gather load: bypass L1 (.cg) + evict_last L2 policy.
__device__ __forceinline__ float4 ldg_gather(const float4* p, unsigned long long pol) {
    float4 v;
    asm("ld.global.cg.L2::cache_hint.v4.f32 {%0,%1,%2,%3}, [%4], %5;"
        : "=f"(v.x), "=f"(v.y), "=f"(v.z), "=f"(v.w) : "l"(p), "l"(pol));
    return v;
}

__device__ __forceinline__ void vmax(float4& m, const float4 v) {
    m.x = fmaxf(m.x, v.x);
    m.y = fmaxf(m.y, v.y);
    m.z = fmaxf(m.z, v.z);
    m.w = fmaxf(m.w, v.w);
}

template <typename IDX>
__device__ __forceinline__ void pool_row(const float4* __restrict__ feat,
                                         const IDX* __restrict__ nm,
                                         float4* __restrict__ outp) {
    const unsigned long long pol = mk_keep_policy();
    // All 27 indices first (2 sectors, warp-uniform broadcast), then all 27
    // gathers issued back-to-back: 27 x 16B = 432 B in flight per thread.
    int idx[KVOL];
    #pragma unroll
    for (int k = 0; k < KVOL; ++k)
        idx[k] = (int)__ldcs(&nm[k]);                  // streaming index read
    float4 v[KVOL];
    #pragma unroll
    for (int k = 0; k < KVOL; ++k)
        v[k] = ldg_gather(feat + (long long)idx[k] * C4, pol);
    float4 m = v[0];
    #pragma unroll
    for (int k = 1; k < KVOL; ++k)
        vmax(m, v[k]);
    __stcs(outp, m);                                   // streaming store
}

// One block per SM-resident slot; reg cap 168 keeps all 27 gathers live.
// Occupancy ~19% is fine: R5->R8 established TLP is in excess and in-flight
// bytes per SM are what close the gap to the LTS/DRAM ceiling.
__global__ __launch_bounds__(C4 * RPB, 1)
void sparse_maxpool_kernel(const float4* __restrict__ in_feat,
                           const void* __restrict__ nmap,
                           float4* __restrict__ out,
                           int n_out, int n_in_rows) {
    // ---- Inline dtype detection (per block; 512B probe, L2-hot) ----
    __shared__ int s_bad;
    int t = threadIdx.y * C4 + threadIdx.x;
    if (t == 0) s_bad = 0;
    __syncthreads();
    if (t < 64) {
        const long long* p = (const long long*)nmap;
        long long v = p[t];
        if (v < 0 || v >= (long long)n_in_rows) atomicOr(&s_bad, 1);
    }
    __syncthreads();
    int is64 = (s_bad == 0);

    int row = blockIdx.x * RPB + threadIdx.y;
    if (row >= n_out) return;
    int c4 = threadIdx.x;                              // 0..23

    const float4* feat_c = in_feat + c4;
    float4* outp = out + (long long)row * C4 + c4;

    if (is64) {
        const long long* nm = (const long long*)nmap + (long long)row * KVOL;
        pool_row(feat_c, nm, outp);
    } else {
        const int* nm = (const int*)nmap + (long long)row * KVOL;
        pool_row(feat_c, nm, outp);
    }
}

extern "C" void kernel_launch(void* const* d_in, const int* in_sizes, int n_in,
                              void* d_out, int out_size) {
    const float4* in_feat = (const float4*)d_in[0];
    const void*   nmap    = (const void*)d_in[1];
    float4*       out     = (float4*)d_out;

    int nmap_elems = in_sizes[1];                      // N_OUT * KVOL
    int n_out      = nmap_elems / KVOL;                // 100000
    int n_in_rows  = in_sizes[0] / 96;                 // 400000

    dim3 block(C4, RPB);
    int grid = (n_out + RPB - 1) / RPB;
    sparse_maxpool_kernel<<<grid, block>>>(in_feat, nmap, out, n_out, n_in_rows);
}

// round 11
// speedup vs baseline: 2.0217x; 1.2908x over previous
#include <cuda_runtime.h>
#include <math_constants.h>

#define KVOL 27
#define C4   24                 // 96 channels = 24 float4
#define RPB  16                 // rows per block: 24*16 = 384 threads

// L2 policy: keep in_feat lines resident (evict-last priority).
__device__ __forceinline__ unsigned long long mk_keep_policy() {
    unsigned long long pol;
    asm("createpolicy.fractional.L2::evict_last.b64 %0, 1.0;" : "=l"(pol));
    return pol;
}

// Gather load: bypass L1 (.cg) + evict_last L2 policy.
__device__ __forceinline__ float4 ldg_gather(const float4* p, unsigned long long pol) {
    float4 v;
    asm("ld.global.cg.L2::cache_hint.v4.f32 {%0,%1,%2,%3}, [%4], %5;"
        : "=f"(v.x), "=f"(v.y), "=f"(v.z), "=f"(v.w) : "l"(p), "l"(pol));
    return v;
}

__device__ __forceinline__ void vmax(float4& m, const float4 v) {
    m.x = fmaxf(m.x, v.x);
    m.y = fmaxf(m.y, v.y);
    m.z = fmaxf(m.z, v.z);
    m.w = fmaxf(m.w, v.w);
}

// Gather B neighbors with all B loads in flight, then reduce.
template <int B, typename IDX>
__device__ __forceinline__ void gather_batch(const float4* __restrict__ feat,
                                             const IDX* __restrict__ nm, int kb,
                                             float4& m, unsigned long long pol) {
    int idx[B];
    #pragma unroll
    for (int j = 0; j < B; ++j)
        idx[j] = (int)__ldcs(&nm[kb + j]);             // streaming index read
    float4 v[B];
    #pragma unroll
    for (int j = 0; j < B; ++j)                        // B x 16B outstanding
        v[j] = ldg_gather(feat + (long long)idx[j] * C4, pol);
    #pragma unroll
    for (int j = 0; j < B; ++j)
        vmax(m, v[j]);
}

template <typename IDX>
__device__ __forceinline__ void pool_row(const float4* __restrict__ feat,
                                         const IDX* __restrict__ nm,
                                         float4* __restrict__ outp) {
    const unsigned long long pol = mk_keep_policy();
    float4 m = make_float4(-CUDART_INF_F, -CUDART_INF_F, -CUDART_INF_F, -CUDART_INF_F);
    gather_batch<9>(feat, nm, 0,  m, pol);             // 3 waves of 9:
    gather_batch<9>(feat, nm, 9,  m, pol);             // same in-flight bytes as
    gather_batch<9>(feat, nm, 18, m, pol);             // R8, +50% warps to issue
    __stcs(outp, m);                                   // streaming store
}

// minBlocks=3 -> reg cap ~56: 9 float4 gathers live per thread, ~36 warps/SM.
// Midpoint of the occupancy/MLP curve (R7=48w/5, R8=24w/14, R10=12w/27).
__global__ __launch_bounds__(C4 * RPB, 3)
void sparse_maxpool_kernel(const float4* __restrict__ in_feat,
                           const void* __restrict__ nmap,
                           float4* __restrict__ out,
                           int n_out, int n_in_rows) {
    // ---- Inline dtype detection (per block; 512B probe, L2-hot) ----
    __shared__ int s_bad;
    int t = threadIdx.y * C4 + threadIdx.x;
    if (t == 0) s_bad = 0;
    __syncthreads();
    if (t < 64) {
        const long long* p = (const long long*)nmap;
        long long v = p[t];
        if (v < 0 || v >= (long long)n_in_rows) atomicOr(&s_bad, 1);
    }
    __syncthreads();
    int is64 = (s_bad == 0);

    int row = blockIdx.x * RPB + threadIdx.y;
    if (row >= n_out) return;
    int c4 = threadIdx.x;                              // 0..23

    const float4* feat_c = in_feat + c4;
    float4* outp = out + (long long)row * C4 + c4;

    if (is64) {
        const long long* nm = (const long long*)nmap + (long long)row * KVOL;
        pool_row(feat_c, nm, outp);
    } else {
        const int* nm = (const int*)nmap + (long long)row * KVOL;
        pool_row(feat_c, nm, outp);
    }
}

extern "C" void kernel_launch(void* const* d_in, const int* in_sizes, int n_in,
                              void* d_out, int out_size) {
    const float4* in_feat = (const float4*)d_in[0];
    const void*   nmap    = (const void*)d_in[1];
    float4*       out     = (float4*)d_out;

    int nmap_elems = in_sizes[1];                      // N_OUT * KVOL
    int n_out      = nmap_elems / KVOL;                // 100000
    int n_in_rows  = in_sizes[0] / 96;                 // 400000

    dim3 block(C4, RPB);
    int grid = (n_out + RPB - 1) / RPB;
    sparse_maxpool_kernel<<<grid, block>>>(in_feat, nmap, out, n_out, n_in_rows);
}